// round 1
// baseline (speedup 1.0000x reference)
#include <cuda_runtime.h>
#include <cuda_bf16.h>
#include <math.h>

// Problem constants
#define N_OBJ   25
#define OBJ_F   4
#define Q_F     11
#define HID     256
#define N_CLS   10
#define NPAIR   (N_OBJ * N_OBJ)   // 625
#define MAXB    1024

#define ROWS    64                 // pair-rows per CTA in main GEMM
#define NTILES  ((NPAIR + ROWS - 1) / ROWS)  // 10
#define KT      32                 // K-slice for weight staging

// Scratch (static device arrays; no allocation allowed)
__device__ float d_u [MAXB * N_OBJ * HID];   // img[b,c] @ g_w1[0:4]
__device__ float d_v [MAXB * N_OBJ * HID];   // img[b,a] @ g_w1[4:8]
__device__ float d_qv[MAXB * HID];           // qst @ g_w1[8:19] + g_b1
__device__ float d_xg[MAXB * HID];           // sum over pairs of g-output

// ---------------------------------------------------------------------------
// Kernel A: per-batch precompute of u, v, qv; also zeroes d_xg.
// grid = B blocks, 256 threads. Thread n owns hidden unit n.
// ---------------------------------------------------------------------------
__global__ void prep_kernel(const float* __restrict__ img,
                            const float* __restrict__ qst,
                            const float* __restrict__ g_w1,
                            const float* __restrict__ g_b1)
{
    int b = blockIdx.x;
    int n = threadIdx.x;  // 0..255

    __shared__ float img_s[N_OBJ * OBJ_F];
    __shared__ float qst_s[Q_F];
    if (n < N_OBJ * OBJ_F) img_s[n] = img[b * (N_OBJ * OBJ_F) + n];
    if (n < Q_F)           qst_s[n] = qst[b * Q_F + n];
    __syncthreads();

    float wi[OBJ_F], wj[OBJ_F];
#pragma unroll
    for (int k = 0; k < OBJ_F; k++) {
        wi[k] = g_w1[(k)         * HID + n];
        wj[k] = g_w1[(OBJ_F + k) * HID + n];
    }
    float qv = g_b1[n];
#pragma unroll
    for (int k = 0; k < Q_F; k++)
        qv += qst_s[k] * g_w1[(2 * OBJ_F + k) * HID + n];

    d_qv[b * HID + n] = qv;
    d_xg[b * HID + n] = 0.0f;

#pragma unroll 5
    for (int c = 0; c < N_OBJ; c++) {
        const float* o = &img_s[c * OBJ_F];
        float uu = o[0] * wi[0] + o[1] * wi[1] + o[2] * wi[2] + o[3] * wi[3];
        float vv = o[0] * wj[0] + o[1] * wj[1] + o[2] * wj[2] + o[3] * wj[3];
        d_u[(b * N_OBJ + c) * HID + n] = uu;
        d_v[(b * N_OBJ + c) * HID + n] = vv;
    }
}

// ---------------------------------------------------------------------------
// Kernel B: main fused g-MLP (layers 2..4) + pair-sum reduction.
// grid = (NTILES, B), 256 threads. Each CTA: 64 pair-rows x 256 cols.
// Thread (tx=tid&31, ty=tid>>5) computes an 8x8 micro-tile:
//   rows r = ty*8 + j, cols c = tx + 32*i  (conflict-free smem patterns)
// ---------------------------------------------------------------------------
extern __shared__ float smem_b[];

__global__ void __launch_bounds__(256, 2)
rn_main_kernel(const float* __restrict__ w2, const float* __restrict__ b2,
               const float* __restrict__ w3, const float* __restrict__ b3,
               const float* __restrict__ w4, const float* __restrict__ b4)
{
    const int tile = blockIdx.x;
    const int b    = blockIdx.y;
    const int tid  = threadIdx.x;
    const int tx   = tid & 31;
    const int ty   = tid >> 5;

    float* h    = smem_b;                      // ROWS*HID      = 16384 f
    float* ws   = smem_b + ROWS * HID;         // KT*HID        =  8192 f
    float* ssum = ws + KT * HID;               // HID           =   256 f

    ssum[tid] = 0.0f;

    const int p0 = tile * ROWS;
    const float* ub  = d_u  + b * N_OBJ * HID;
    const float* vb  = d_v  + b * N_OBJ * HID;
    const float* qvb = d_qv + b * HID;

    // ---- build h1 = relu(u[c_obj] + v[a] + qv), zero for padded rows ----
#pragma unroll
    for (int j = 0; j < 8; j++) {
        int r = ty * 8 + j;
        int p = p0 + r;
        bool valid = (p < NPAIR);
        int a  = valid ? (p / N_OBJ) : 0;
        int co = valid ? (p - a * N_OBJ) : 0;
#pragma unroll
        for (int i = 0; i < 8; i++) {
            int c = tx + 32 * i;
            float val = 0.0f;
            if (valid)
                val = fmaxf(ub[co * HID + c] + vb[a * HID + c] + qvb[c], 0.0f);
            h[r * HID + c] = val;
        }
    }
    __syncthreads();

    const float* Ws[3] = { w2, w3, w4 };
    const float* Bs[3] = { b2, b3, b4 };

    for (int L = 0; L < 3; L++) {
        float acc[8][8];
#pragma unroll
        for (int j = 0; j < 8; j++)
#pragma unroll
            for (int i = 0; i < 8; i++) acc[j][i] = 0.0f;

        const float* W = Ws[L];
        for (int k0 = 0; k0 < HID; k0 += KT) {
            __syncthreads();  // prior consumers of ws done / h writes visible
            // stage W[k0:k0+KT, :] -> ws (coalesced float4)
            const float4* Wv  = (const float4*)(W + k0 * HID);
            float4*       wsv = (float4*)ws;
#pragma unroll
            for (int q = 0; q < (KT * HID / 4) / 256; q++)
                wsv[tid + 256 * q] = Wv[tid + 256 * q];
            __syncthreads();

#pragma unroll
            for (int kk = 0; kk < KT; kk++) {
                float hv[8], wv[8];
#pragma unroll
                for (int j = 0; j < 8; j++)
                    hv[j] = h[(ty * 8 + j) * HID + k0 + kk];   // broadcast
#pragma unroll
                for (int i = 0; i < 8; i++)
                    wv[i] = ws[kk * HID + tx + 32 * i];        // conflict-free
#pragma unroll
                for (int j = 0; j < 8; j++)
#pragma unroll
                    for (int i = 0; i < 8; i++)
                        acc[j][i] += hv[j] * wv[i];
            }
        }

        // bias + relu
        const float* Bb = Bs[L];
        float bb[8];
#pragma unroll
        for (int i = 0; i < 8; i++) bb[i] = Bb[tx + 32 * i];
#pragma unroll
        for (int j = 0; j < 8; j++)
#pragma unroll
            for (int i = 0; i < 8; i++)
                acc[j][i] = fmaxf(acc[j][i] + bb[i], 0.0f);

        __syncthreads();  // all reads of h done before overwrite

        if (L < 2) {
#pragma unroll
            for (int j = 0; j < 8; j++) {
                int r = ty * 8 + j;
#pragma unroll
                for (int i = 0; i < 8; i++)
                    h[r * HID + tx + 32 * i] = acc[j][i];
            }
            // next-iteration leading __syncthreads publishes these writes
        } else {
            // reduce over this CTA's valid rows, then into d_xg
#pragma unroll
            for (int i = 0; i < 8; i++) {
                float s = 0.0f;
#pragma unroll
                for (int j = 0; j < 8; j++) {
                    int p = p0 + ty * 8 + j;
                    if (p < NPAIR) s += acc[j][i];
                }
                atomicAdd(&ssum[tx + 32 * i], s);
            }
            __syncthreads();
            atomicAdd(&d_xg[b * HID + tid], ssum[tid]);
        }
    }
}

// ---------------------------------------------------------------------------
// Kernel C: f-MLP + log_softmax. grid = B/8 blocks, 256 threads, 8 batches/CTA
// (amortizes weight reads through L2/L1).
// ---------------------------------------------------------------------------
__global__ void fnet_kernel(const float* __restrict__ fw1, const float* __restrict__ fb1,
                            const float* __restrict__ fw2, const float* __restrict__ fb2,
                            const float* __restrict__ fw3, const float* __restrict__ fb3,
                            const float* __restrict__ fw4, const float* __restrict__ fb4,
                            float* __restrict__ out, int B)
{
    const int n   = threadIdx.x;    // 0..255
    const int bb0 = blockIdx.x * 8;

    __shared__ float xa[8][HID];
    __shared__ float xb[8][HID];
    __shared__ float logit[8][16];

#pragma unroll
    for (int m = 0; m < 8; m++) {
        float v = 0.0f;
        if (bb0 + m < B) v = d_xg[(bb0 + m) * HID + n];
        xa[m][n] = v;
    }
    __syncthreads();

    float (*src)[HID] = xa;
    float (*dst)[HID] = xb;
    const float* Ws[3] = { fw1, fw2, fw3 };
    const float* Bs[3] = { fb1, fb2, fb3 };

    for (int L = 0; L < 3; L++) {
        float acc[8];
#pragma unroll
        for (int m = 0; m < 8; m++) acc[m] = 0.0f;
        const float* W = Ws[L];
        for (int k = 0; k < HID; k++) {
            float w = W[k * HID + n];          // coalesced across threads
#pragma unroll
            for (int m = 0; m < 8; m++)
                acc[m] += src[m][k] * w;       // broadcast smem read
        }
        float bv = Bs[L][n];
#pragma unroll
        for (int m = 0; m < 8; m++)
            dst[m][n] = fmaxf(acc[m] + bv, 0.0f);
        __syncthreads();
        float (*t)[HID] = src; src = dst; dst = t;
    }

    // logits: 8 batches x 10 classes = 80 outputs
    if (n < 8 * N_CLS) {
        int m = n / N_CLS, c = n % N_CLS;
        float acc = fb4[c];
        for (int k = 0; k < HID; k++)
            acc += src[m][k] * fw4[k * N_CLS + c];
        logit[m][c] = acc;
    }
    __syncthreads();

    if (n < 8 && (bb0 + n) < B) {
        float mx = -INFINITY;
#pragma unroll
        for (int c = 0; c < N_CLS; c++) mx = fmaxf(mx, logit[n][c]);
        float s = 0.0f;
#pragma unroll
        for (int c = 0; c < N_CLS; c++) s += expf(logit[n][c] - mx);
        float lse = mx + logf(s);
#pragma unroll
        for (int c = 0; c < N_CLS; c++)
            out[(bb0 + n) * N_CLS + c] = logit[n][c] - lse;
    }
}

// ---------------------------------------------------------------------------
extern "C" void kernel_launch(void* const* d_in, const int* in_sizes, int n_in,
                              void* d_out, int out_size)
{
    const float* img  = (const float*)d_in[0];
    const float* qst  = (const float*)d_in[1];
    const float* g_w1 = (const float*)d_in[2];
    const float* g_b1 = (const float*)d_in[3];
    const float* g_w2 = (const float*)d_in[4];
    const float* g_b2 = (const float*)d_in[5];
    const float* g_w3 = (const float*)d_in[6];
    const float* g_b3 = (const float*)d_in[7];
    const float* g_w4 = (const float*)d_in[8];
    const float* g_b4 = (const float*)d_in[9];
    const float* f_w1 = (const float*)d_in[10];
    const float* f_b1 = (const float*)d_in[11];
    const float* f_w2 = (const float*)d_in[12];
    const float* f_b2 = (const float*)d_in[13];
    const float* f_w3 = (const float*)d_in[14];
    const float* f_b3 = (const float*)d_in[15];
    const float* f_w4 = (const float*)d_in[16];
    const float* f_b4 = (const float*)d_in[17];
    float* out = (float*)d_out;

    int B = in_sizes[0] / (N_OBJ * OBJ_F);
    if (B > MAXB) B = MAXB;

    const size_t smem_main = (size_t)(ROWS * HID + KT * HID + HID) * sizeof(float);
    cudaFuncSetAttribute(rn_main_kernel,
                         cudaFuncAttributeMaxDynamicSharedMemorySize,
                         (int)smem_main);

    prep_kernel<<<B, 256>>>(img, qst, g_w1, g_b1);

    dim3 gridB(NTILES, B);
    rn_main_kernel<<<gridB, 256, smem_main>>>(g_w2, g_b2, g_w3, g_b3, g_w4, g_b4);

    fnet_kernel<<<(B + 7) / 8, 256>>>(f_w1, f_b1, f_w2, f_b2, f_w3, f_b3,
                                      f_w4, f_b4, out, B);
}

// round 3
// speedup vs baseline: 3.1429x; 3.1429x over previous
#include <cuda_runtime.h>
#include <cuda.h>
#include <cuda_bf16.h>
#include <math.h>
#include <stdint.h>

// ---------------- problem constants ----------------
#define N_OBJ   25
#define OBJ_F   4
#define Q_F     11
#define HID     256
#define N_CLS   10
#define NPAIR   (N_OBJ * N_OBJ)      // 625
#define MAXB    1024
#define TILE_M  128
#define NT      5                    // ceil(625/128)

// A-frag smem layout: A[kb][m*8 + kperm], kb = k/8 (32 blocks), pad 4 floats/block
#define AKB     1028                 // floats per kb block (128*8 + 4 pad)
#define SMA_F   (32 * AKB)           // 32896 floats
#define SMB_F   8192                 // one 32KB weight chunk (4 k-steps x 32 n-tiles x 64)
// smem float offsets
#define OFF_A    0
#define OFF_B0   SMA_F
#define OFF_B1   (SMA_F + SMB_F)
#define OFF_BIAS (SMA_F + 2 * SMB_F)       // 3*256
#define OFF_SSUM (OFF_BIAS + 768)          // 256
#define SMEM_FLOATS (OFF_SSUM + 256)       // 50304 floats = 201216 B

// ---------------- scratch ----------------
__device__ float d_u [MAXB * N_OBJ * HID];
__device__ float d_v [MAXB * N_OBJ * HID];
__device__ float d_qv[MAXB * HID];
__device__ float d_xg[MAXB * HID];
// weights pre-arranged in B-fragment order:
// d_wf[((L*32 + s)*32 + j)*64 + lane*2 + {0,1}] = W[s*8 + lane%4 (+4)][j*8 + lane/4]
__device__ float d_wf[3 * 32 * 32 * 64];

__device__ __forceinline__ int kperm(int k) { return ((k & 3) << 1) | ((k >> 2) & 1); }

__device__ __forceinline__ uint32_t smem_u32(const void* p) {
    uint32_t a;
    asm("{ .reg .u64 t; cvta.to.shared.u64 t, %1; cvt.u32.u64 %0, t; }" : "=r"(a) : "l"(p));
    return a;
}

// ---------------------------------------------------------------------------
// prep: per-batch u, v, qv; zero d_xg
// ---------------------------------------------------------------------------
__global__ void prep_kernel(const float* __restrict__ img, const float* __restrict__ qst,
                            const float* __restrict__ g_w1, const float* __restrict__ g_b1)
{
    int b = blockIdx.x, n = threadIdx.x;
    __shared__ float img_s[N_OBJ * OBJ_F];
    __shared__ float qst_s[Q_F];
    if (n < N_OBJ * OBJ_F) img_s[n] = img[b * (N_OBJ * OBJ_F) + n];
    if (n < Q_F)           qst_s[n] = qst[b * Q_F + n];
    __syncthreads();

    float wi[OBJ_F], wj[OBJ_F];
#pragma unroll
    for (int k = 0; k < OBJ_F; k++) {
        wi[k] = g_w1[k * HID + n];
        wj[k] = g_w1[(OBJ_F + k) * HID + n];
    }
    float qv = g_b1[n];
#pragma unroll
    for (int k = 0; k < Q_F; k++) qv += qst_s[k] * g_w1[(2 * OBJ_F + k) * HID + n];
    d_qv[b * HID + n] = qv;
    d_xg[b * HID + n] = 0.0f;

#pragma unroll 5
    for (int c = 0; c < N_OBJ; c++) {
        const float* o = &img_s[c * OBJ_F];
        d_u[(b * N_OBJ + c) * HID + n] = o[0]*wi[0] + o[1]*wi[1] + o[2]*wi[2] + o[3]*wi[3];
        d_v[(b * N_OBJ + c) * HID + n] = o[0]*wj[0] + o[1]*wj[1] + o[2]*wj[2] + o[3]*wj[3];
    }
}

// ---------------------------------------------------------------------------
// pre-arrange g_w2..4 into B-fragment order
// ---------------------------------------------------------------------------
__global__ void prearrange_w(const float* __restrict__ w2, const float* __restrict__ w3,
                             const float* __restrict__ w4)
{
    int lane = threadIdx.x;           // 0..31
    int idx  = blockIdx.x;            // 0..3071 : (L, s, j)
    int j = idx & 31, s = (idx >> 5) & 31, L = idx >> 10;
    const float* W = (L == 0) ? w2 : (L == 1) ? w3 : w4;
    int k0 = s * 8 + (lane & 3);
    int n  = j * 8 + (lane >> 2);
    float* dst = d_wf + (size_t)idx * 64 + lane * 2;
    dst[0] = W[k0 * HID + n];
    dst[1] = W[(k0 + 4) * HID + n];
}

// ---------------------------------------------------------------------------
// main fused tf32 mma.sync kernel: grid (5, B), 256 threads (8 warps, 64x64 tiles)
// ---------------------------------------------------------------------------
extern __shared__ float smf[];

__device__ __forceinline__ void stage_chunk(uint32_t sb_bytes, int i, int tid)
{
    // copy chunk i (8192 floats) from d_wf into buffer (i&1)
    const float* src = d_wf + (size_t)i * SMB_F;
    uint32_t dstb = sb_bytes + (uint32_t)(((i & 1) ? OFF_B1 : OFF_B0) * 4);
#pragma unroll
    for (int q = 0; q < 8; q++) {
        int o = (tid + q * 256) * 4;    // float index, 16B granularity
        asm volatile("cp.async.cg.shared.global [%0], [%1], 16;"
                     :: "r"(dstb + o * 4), "l"(src + o));
    }
    asm volatile("cp.async.commit_group;" ::: "memory");
}

__device__ __forceinline__ void mma_tf32(float* d, const float2 a_lo, const float2 a_hi,
                                         const float2 bfr)
{
    // a0=(m, k=t)=a_lo.x  a1=(m+8,k=t)=a_hi.x  a2=(m,k=t+4)=a_lo.y  a3=(m+8,k=t+4)=a_hi.y
    asm volatile(
        "mma.sync.aligned.m16n8k8.row.col.f32.tf32.tf32.f32 "
        "{%0,%1,%2,%3}, {%4,%5,%6,%7}, {%8,%9}, {%0,%1,%2,%3};"
        : "+f"(d[0]), "+f"(d[1]), "+f"(d[2]), "+f"(d[3])
        : "r"(__float_as_uint(a_lo.x)), "r"(__float_as_uint(a_hi.x)),
          "r"(__float_as_uint(a_lo.y)), "r"(__float_as_uint(a_hi.y)),
          "r"(__float_as_uint(bfr.x)),  "r"(__float_as_uint(bfr.y)));
}

__global__ void __launch_bounds__(256, 1)
rn_mma_kernel(const float* __restrict__ b2, const float* __restrict__ b3,
              const float* __restrict__ b4)
{
    const int tile = blockIdx.x;
    const int b    = blockIdx.y;
    const int tid  = threadIdx.x;
    const int lane = tid & 31, w = tid >> 5;
    const int wm = w >> 2, wn = w & 3;      // warp tile: rows wm*64, cols wn*64
    const int g = lane >> 2, t = lane & 3;
    const uint32_t sb = smem_u32(smf);

    float* A    = smf + OFF_A;
    float* bias = smf + OFF_BIAS;
    float* ssum = smf + OFF_SSUM;

    // ---- stage u, v (overlay B buffers), biases ----
    float* us = smf + OFF_B0;               // 6400 floats
    float* vs = smf + OFF_B0 + N_OBJ * HID; // 6400 floats (fits in 16384)
    {
        const float* ub = d_u + (size_t)b * N_OBJ * HID;
        const float* vb = d_v + (size_t)b * N_OBJ * HID;
        for (int i = tid; i < N_OBJ * HID; i += 256) { us[i] = ub[i]; vs[i] = vb[i]; }
        bias[tid]       = b2[tid];
        bias[256 + tid] = b3[tid];
        bias[512 + tid] = b4[tid];
        ssum[tid] = 0.0f;
    }
    __syncthreads();

    // ---- build h1 = relu(u[c_obj] + v[a] + qv) in A-frag layout ----
    {
        int c = tid;                         // column (= k of layer 2)
        float qvc = d_qv[(size_t)b * HID + c];
        int base = (c >> 3) * AKB + kperm(c & 7);
        for (int r = 0; r < TILE_M; r++) {
            int p = tile * TILE_M + r;
            float val = 0.0f;
            if (p < NPAIR) {
                int a  = p / N_OBJ;
                int co = p - a * N_OBJ;
                val = fmaxf(us[co * HID + c] + vs[a * HID + c] + qvc, 0.0f);
            }
            A[base + r * 8] = val;
        }
    }
    __syncthreads();   // u/v reads done; B region free

    stage_chunk(sb, 0, tid);

    float acc[4][8][4];
#pragma unroll
    for (int mt = 0; mt < 4; mt++)
#pragma unroll
        for (int j2 = 0; j2 < 8; j2++)
#pragma unroll
            for (int c4 = 0; c4 < 4; c4++) acc[mt][j2][c4] = 0.0f;

    for (int i = 0; i < 24; i++) {
        const int L  = i >> 3;
        const int cs = i & 7;
        if (i + 1 < 24) { stage_chunk(sb, i + 1, tid);
                          asm volatile("cp.async.wait_group 1;" ::: "memory"); }
        else            { asm volatile("cp.async.wait_group 0;" ::: "memory"); }
        __syncthreads();                     // chunk i ready; A writes visible

        const float* buf = smf + ((i & 1) ? OFF_B1 : OFF_B0);
#pragma unroll
        for (int sl = 0; sl < 4; sl++) {
            const int kb = cs * 4 + sl;
            float2 a_lo[4], a_hi[4];
#pragma unroll
            for (int mt = 0; mt < 4; mt++) {
                int m0 = wm * 64 + mt * 16 + g;
                a_lo[mt] = *(const float2*)&A[kb * AKB + m0 * 8 + 2 * t];
                a_hi[mt] = *(const float2*)&A[kb * AKB + (m0 + 8) * 8 + 2 * t];
            }
            float2 bfr[8];
#pragma unroll
            for (int j2 = 0; j2 < 8; j2++)
                bfr[j2] = *(const float2*)&buf[((sl * 32) + wn * 8 + j2) * 64 + lane * 2];
#pragma unroll
            for (int mt = 0; mt < 4; mt++)
#pragma unroll
                for (int j2 = 0; j2 < 8; j2++)
                    mma_tf32(acc[mt][j2], a_lo[mt], a_hi[mt], bfr[j2]);
        }

        if (cs == 7) {
            __syncthreads();                 // all reads of A done before overwrite
            if (L < 2) {
                const float* bb = bias + L * 256;
#pragma unroll
                for (int mt = 0; mt < 4; mt++) {
                    int m0 = wm * 64 + mt * 16 + g;
#pragma unroll
                    for (int j2 = 0; j2 < 8; j2++) {
                        int n0  = wn * 64 + j2 * 8 + 2 * t;
                        int kb  = n0 >> 3;
                        int kp0 = kperm(n0 & 7), kp1 = kperm((n0 + 1) & 7);
                        float v0 = fmaxf(acc[mt][j2][0] + bb[n0],     0.f);
                        float v1 = fmaxf(acc[mt][j2][1] + bb[n0 + 1], 0.f);
                        float v2 = fmaxf(acc[mt][j2][2] + bb[n0],     0.f);
                        float v3 = fmaxf(acc[mt][j2][3] + bb[n0 + 1], 0.f);
                        A[kb * AKB + m0 * 8 + kp0]       = v0;
                        A[kb * AKB + m0 * 8 + kp1]       = v1;
                        A[kb * AKB + (m0 + 8) * 8 + kp0] = v2;
                        A[kb * AKB + (m0 + 8) * 8 + kp1] = v3;
                        acc[mt][j2][0] = acc[mt][j2][1] = 0.f;
                        acc[mt][j2][2] = acc[mt][j2][3] = 0.f;
                    }
                }
            } else {
                // final layer: relu + bias, mask invalid rows, column partial sums
                const float* bb = bias + 512;
#pragma unroll
                for (int j2 = 0; j2 < 8; j2++) {
                    int n0 = wn * 64 + j2 * 8 + 2 * t;
                    float p0 = 0.f, p1 = 0.f;
#pragma unroll
                    for (int mt = 0; mt < 4; mt++) {
                        int m0 = wm * 64 + mt * 16 + g;
                        bool v_lo = (tile * TILE_M + m0)     < NPAIR;
                        bool v_hi = (tile * TILE_M + m0 + 8) < NPAIR;
                        if (v_lo) { p0 += fmaxf(acc[mt][j2][0] + bb[n0],     0.f);
                                    p1 += fmaxf(acc[mt][j2][1] + bb[n0 + 1], 0.f); }
                        if (v_hi) { p0 += fmaxf(acc[mt][j2][2] + bb[n0],     0.f);
                                    p1 += fmaxf(acc[mt][j2][3] + bb[n0 + 1], 0.f); }
                    }
                    atomicAdd(&ssum[n0],     p0);
                    atomicAdd(&ssum[n0 + 1], p1);
                }
            }
        }
        __syncthreads();
    }

    atomicAdd(&d_xg[(size_t)b * HID + tid], ssum[tid]);
}

// ---------------------------------------------------------------------------
// f-MLP + log_softmax
// ---------------------------------------------------------------------------
__global__ void fnet_kernel(const float* __restrict__ fw1, const float* __restrict__ fb1,
                            const float* __restrict__ fw2, const float* __restrict__ fb2,
                            const float* __restrict__ fw3, const float* __restrict__ fb3,
                            const float* __restrict__ fw4, const float* __restrict__ fb4,
                            float* __restrict__ out, int B)
{
    const int n = threadIdx.x;
    const int bb0 = blockIdx.x * 8;
    __shared__ float xa[8][HID];
    __shared__ float xb[8][HID];
    __shared__ float logit[8][16];

#pragma unroll
    for (int m = 0; m < 8; m++) {
        float v = 0.0f;
        if (bb0 + m < B) v = d_xg[(bb0 + m) * HID + n];
        xa[m][n] = v;
    }
    __syncthreads();

    float (*src)[HID] = xa;
    float (*dst)[HID] = xb;
    const float* Ws[3] = { fw1, fw2, fw3 };
    const float* Bs[3] = { fb1, fb2, fb3 };
    for (int L = 0; L < 3; L++) {
        float acc[8];
#pragma unroll
        for (int m = 0; m < 8; m++) acc[m] = 0.0f;
        const float* W = Ws[L];
        for (int k = 0; k < HID; k++) {
            float wv = W[k * HID + n];
#pragma unroll
            for (int m = 0; m < 8; m++) acc[m] += src[m][k] * wv;
        }
        float bv = Bs[L][n];
#pragma unroll
        for (int m = 0; m < 8; m++) dst[m][n] = fmaxf(acc[m] + bv, 0.0f);
        __syncthreads();
        float (*tp)[HID] = src; src = dst; dst = tp;
    }

    if (n < 8 * N_CLS) {
        int m = n / N_CLS, c = n % N_CLS;
        float acc = fb4[c];
        for (int k = 0; k < HID; k++) acc += src[m][k] * fw4[k * N_CLS + c];
        logit[m][c] = acc;
    }
    __syncthreads();

    if (n < 8 && (bb0 + n) < B) {
        float mx = -INFINITY;
#pragma unroll
        for (int c = 0; c < N_CLS; c++) mx = fmaxf(mx, logit[n][c]);
        float s = 0.0f;
#pragma unroll
        for (int c = 0; c < N_CLS; c++) s += expf(logit[n][c] - mx);
        float lse = mx + logf(s);
#pragma unroll
        for (int c = 0; c < N_CLS; c++) out[(bb0 + n) * N_CLS + c] = logit[n][c] - lse;
    }
}

// ---------------------------------------------------------------------------
extern "C" void kernel_launch(void* const* d_in, const int* in_sizes, int n_in,
                              void* d_out, int out_size)
{
    const float* img  = (const float*)d_in[0];
    const float* qst  = (const float*)d_in[1];
    const float* g_w1 = (const float*)d_in[2];
    const float* g_b1 = (const float*)d_in[3];
    const float* g_w2 = (const float*)d_in[4];
    const float* g_b2 = (const float*)d_in[5];
    const float* g_w3 = (const float*)d_in[6];
    const float* g_b3 = (const float*)d_in[7];
    const float* g_w4 = (const float*)d_in[8];
    const float* g_b4 = (const float*)d_in[9];
    const float* f_w1 = (const float*)d_in[10];
    const float* f_b1 = (const float*)d_in[11];
    const float* f_w2 = (const float*)d_in[12];
    const float* f_b2 = (const float*)d_in[13];
    const float* f_w3 = (const float*)d_in[14];
    const float* f_b3 = (const float*)d_in[15];
    const float* f_w4 = (const float*)d_in[16];
    const float* f_b4 = (const float*)d_in[17];
    float* out = (float*)d_out;

    int B = in_sizes[0] / (N_OBJ * OBJ_F);
    if (B > MAXB) B = MAXB;

    const int smem_bytes = SMEM_FLOATS * 4;   // 201216
    cudaFuncSetAttribute(rn_mma_kernel, cudaFuncAttributeMaxDynamicSharedMemorySize,
                         smem_bytes);

    prearrange_w<<<3072, 32>>>(g_w2, g_w3, g_w4);
    prep_kernel<<<B, 256>>>(img, qst, g_w1, g_b1);
    rn_mma_kernel<<<dim3(NT, B), 256, smem_bytes>>>(g_b2, g_b3, g_b4);
    fnet_kernel<<<(B + 7) / 8, 256>>>(f_w1, f_b1, f_w2, f_b2, f_w3, f_b3, f_w4, f_b4, out, B);
}

// round 4
// speedup vs baseline: 3.1837x; 1.0130x over previous
#include <cuda_runtime.h>
#include <cuda.h>
#include <cuda_bf16.h>
#include <math.h>
#include <stdint.h>

// ---------------- problem constants ----------------
#define N_OBJ   25
#define OBJ_F   4
#define Q_F     11
#define HID     256
#define N_CLS   10
#define NPAIR   (N_OBJ * N_OBJ)      // 625
#define MAXB    1024
#define TILE_M  128
#define NT      5                    // ceil(625/128)
#define NTHREADS 512

// A-frag smem layout: A[kb][m*8 + kperm], kb = k/8 (32 blocks), pad 4 floats/block
#define AKB     1028
#define SMA_F   (32 * AKB)           // 32896 floats
#define SMB_F   8192                 // one 32KB weight chunk
#define OFF_A    0
#define OFF_B0   SMA_F
#define OFF_B1   (SMA_F + SMB_F)
#define OFF_BIAS (SMA_F + 2 * SMB_F)
#define OFF_SSUM (OFF_BIAS + 768)
#define SMEM_FLOATS (OFF_SSUM + 256)       // 50304 floats = 201216 B

// ---------------- scratch ----------------
__device__ float d_u [MAXB * N_OBJ * HID];
__device__ float d_v [MAXB * N_OBJ * HID];
__device__ float d_qv[MAXB * HID];
__device__ float d_xg[MAXB * HID];
// weights pre-arranged in B-fragment order:
// d_wf[((L*32 + s)*32 + j)*64 + lane*2 + {0,1}] = W[s*8 + lane%4 (+4)][j*8 + lane/4]
__device__ float d_wf[3 * 32 * 32 * 64];

__device__ __forceinline__ int kperm(int k) { return ((k & 3) << 1) | ((k >> 2) & 1); }

__device__ __forceinline__ uint32_t smem_u32(const void* p) {
    uint32_t a;
    asm("{ .reg .u64 t; cvta.to.shared.u64 t, %1; cvt.u32.u64 %0, t; }" : "=r"(a) : "l"(p));
    return a;
}

// ---------------------------------------------------------------------------
// prep: per-batch u, v, qv; zero d_xg
// ---------------------------------------------------------------------------
__global__ void prep_kernel(const float* __restrict__ img, const float* __restrict__ qst,
                            const float* __restrict__ g_w1, const float* __restrict__ g_b1)
{
    int b = blockIdx.x, n = threadIdx.x;
    __shared__ float img_s[N_OBJ * OBJ_F];
    __shared__ float qst_s[Q_F];
    if (n < N_OBJ * OBJ_F) img_s[n] = img[b * (N_OBJ * OBJ_F) + n];
    if (n < Q_F)           qst_s[n] = qst[b * Q_F + n];
    __syncthreads();

    float wi[OBJ_F], wj[OBJ_F];
#pragma unroll
    for (int k = 0; k < OBJ_F; k++) {
        wi[k] = g_w1[k * HID + n];
        wj[k] = g_w1[(OBJ_F + k) * HID + n];
    }
    float qv = g_b1[n];
#pragma unroll
    for (int k = 0; k < Q_F; k++) qv += qst_s[k] * g_w1[(2 * OBJ_F + k) * HID + n];
    d_qv[b * HID + n] = qv;
    d_xg[b * HID + n] = 0.0f;

#pragma unroll 5
    for (int c = 0; c < N_OBJ; c++) {
        const float* o = &img_s[c * OBJ_F];
        d_u[(b * N_OBJ + c) * HID + n] = o[0]*wi[0] + o[1]*wi[1] + o[2]*wi[2] + o[3]*wi[3];
        d_v[(b * N_OBJ + c) * HID + n] = o[0]*wj[0] + o[1]*wj[1] + o[2]*wj[2] + o[3]*wj[3];
    }
}

// ---------------------------------------------------------------------------
// pre-arrange g_w2..4 into B-fragment order
// ---------------------------------------------------------------------------
__global__ void prearrange_w(const float* __restrict__ w2, const float* __restrict__ w3,
                             const float* __restrict__ w4)
{
    int lane = threadIdx.x;
    int idx  = blockIdx.x;            // (L, s, j)
    int j = idx & 31, s = (idx >> 5) & 31, L = idx >> 10;
    const float* W = (L == 0) ? w2 : (L == 1) ? w3 : w4;
    int k0 = s * 8 + (lane & 3);
    int n  = j * 8 + (lane >> 2);
    float* dst = d_wf + (size_t)idx * 64 + lane * 2;
    dst[0] = W[k0 * HID + n];
    dst[1] = W[(k0 + 4) * HID + n];
}

// ---------------------------------------------------------------------------
// main fused tf32 mma.sync kernel: grid (5, B), 512 threads (16 warps, 32x64)
// ---------------------------------------------------------------------------
extern __shared__ float smf[];

__device__ __forceinline__ void stage_chunk(uint32_t sb_bytes, int i, int tid)
{
    const float* src = d_wf + (size_t)i * SMB_F;
    uint32_t dstb = sb_bytes + (uint32_t)(((i & 1) ? OFF_B1 : OFF_B0) * 4);
#pragma unroll
    for (int q = 0; q < 4; q++) {
        int o = (tid + q * NTHREADS) * 4;
        asm volatile("cp.async.cg.shared.global [%0], [%1], 16;"
                     :: "r"(dstb + o * 4), "l"(src + o));
    }
    asm volatile("cp.async.commit_group;" ::: "memory");
}

__device__ __forceinline__ void mma_tf32(float* d, const float2 a_lo, const float2 a_hi,
                                         const float2 bfr)
{
    asm volatile(
        "mma.sync.aligned.m16n8k8.row.col.f32.tf32.tf32.f32 "
        "{%0,%1,%2,%3}, {%4,%5,%6,%7}, {%8,%9}, {%0,%1,%2,%3};"
        : "+f"(d[0]), "+f"(d[1]), "+f"(d[2]), "+f"(d[3])
        : "r"(__float_as_uint(a_lo.x)), "r"(__float_as_uint(a_hi.x)),
          "r"(__float_as_uint(a_lo.y)), "r"(__float_as_uint(a_hi.y)),
          "r"(__float_as_uint(bfr.x)),  "r"(__float_as_uint(bfr.y)));
}

__global__ void __launch_bounds__(NTHREADS, 1)
rn_mma_kernel(const float* __restrict__ b2, const float* __restrict__ b3,
              const float* __restrict__ b4)
{
    const int tile = blockIdx.x;
    const int b    = blockIdx.y;
    const int tid  = threadIdx.x;
    const int lane = tid & 31, w = tid >> 5;
    const int wm = w >> 2, wn = w & 3;      // warp tile: rows wm*32, cols wn*64
    const int g = lane >> 2, t = lane & 3;
    const uint32_t sb = smem_u32(smf);

    float* A    = smf + OFF_A;
    float* bias = smf + OFF_BIAS;
    float* ssum = smf + OFF_SSUM;

    // ---- stage u, v (overlay B buffers), biases ----
    float* us = smf + OFF_B0;
    float* vs = smf + OFF_B0 + N_OBJ * HID;
    {
        const float* ub = d_u + (size_t)b * N_OBJ * HID;
        const float* vb = d_v + (size_t)b * N_OBJ * HID;
        for (int i = tid; i < N_OBJ * HID; i += NTHREADS) { us[i] = ub[i]; vs[i] = vb[i]; }
        if (tid < 256) {
            bias[tid]       = b2[tid];
            bias[256 + tid] = b3[tid];
            bias[512 + tid] = b4[tid];
            ssum[tid] = 0.0f;
        }
    }
    __syncthreads();

    // ---- build h1 = relu(u[c_obj] + v[a] + qv) in A-frag layout ----
    {
        int c = tid & 255;
        int h = tid >> 8;                    // row-half
        float qvc = d_qv[(size_t)b * HID + c];
        int base = (c >> 3) * AKB + kperm(c & 7);
        int p0i = tile * TILE_M + h * 64;
        int a  = p0i / N_OBJ;
        int co = p0i - a * N_OBJ;
#pragma unroll 4
        for (int r = 0; r < 64; r++) {
            int rr = h * 64 + r;
            float val = 0.0f;
            if (p0i + r < NPAIR)
                val = fmaxf(us[co * HID + c] + vs[a * HID + c] + qvc, 0.0f);
            A[base + rr * 8] = val;
            if (++co == N_OBJ) { co = 0; a++; }
        }
    }
    __syncthreads();   // u/v reads done; B region free

    stage_chunk(sb, 0, tid);

    float acc[2][8][4];
#pragma unroll
    for (int mt = 0; mt < 2; mt++)
#pragma unroll
        for (int j2 = 0; j2 < 8; j2++)
#pragma unroll
            for (int c4 = 0; c4 < 4; c4++) acc[mt][j2][c4] = 0.0f;

    for (int i = 0; i < 24; i++) {
        const int L  = i >> 3;
        const int cs = i & 7;
        if (i + 1 < 24) { stage_chunk(sb, i + 1, tid);
                          asm volatile("cp.async.wait_group 1;" ::: "memory"); }
        else            { asm volatile("cp.async.wait_group 0;" ::: "memory"); }
        __syncthreads();                     // chunk i ready; A writes visible

        const float* buf = smf + ((i & 1) ? OFF_B1 : OFF_B0);
#pragma unroll
        for (int sl = 0; sl < 4; sl++) {
            const int kb = cs * 4 + sl;
            float2 a_lo[2], a_hi[2];
#pragma unroll
            for (int mt = 0; mt < 2; mt++) {
                int m0 = wm * 32 + mt * 16 + g;
                a_lo[mt] = *(const float2*)&A[kb * AKB + m0 * 8 + 2 * t];
                a_hi[mt] = *(const float2*)&A[kb * AKB + (m0 + 8) * 8 + 2 * t];
            }
            float2 bfr[8];
#pragma unroll
            for (int j2 = 0; j2 < 8; j2++)
                bfr[j2] = *(const float2*)&buf[((sl * 32) + wn * 8 + j2) * 64 + lane * 2];
#pragma unroll
            for (int mt = 0; mt < 2; mt++)
#pragma unroll
                for (int j2 = 0; j2 < 8; j2++)
                    mma_tf32(acc[mt][j2], a_lo[mt], a_hi[mt], bfr[j2]);
        }

        if (cs == 7) {
            __syncthreads();                 // all reads of A done before overwrite
            if (L < 2) {
                const float* bb = bias + L * 256;
#pragma unroll
                for (int mt = 0; mt < 2; mt++) {
                    int m0 = wm * 32 + mt * 16 + g;
#pragma unroll
                    for (int j2 = 0; j2 < 8; j2++) {
                        int n0  = wn * 64 + j2 * 8 + 2 * t;
                        int kb  = n0 >> 3;
                        int kp0 = kperm(n0 & 7), kp1 = kperm((n0 + 1) & 7);
                        float v0 = fmaxf(acc[mt][j2][0] + bb[n0],     0.f);
                        float v1 = fmaxf(acc[mt][j2][1] + bb[n0 + 1], 0.f);
                        float v2 = fmaxf(acc[mt][j2][2] + bb[n0],     0.f);
                        float v3 = fmaxf(acc[mt][j2][3] + bb[n0 + 1], 0.f);
                        A[kb * AKB + m0 * 8 + kp0]       = v0;
                        A[kb * AKB + m0 * 8 + kp1]       = v1;
                        A[kb * AKB + (m0 + 8) * 8 + kp0] = v2;
                        A[kb * AKB + (m0 + 8) * 8 + kp1] = v3;
                        acc[mt][j2][0] = acc[mt][j2][1] = 0.f;
                        acc[mt][j2][2] = acc[mt][j2][3] = 0.f;
                    }
                }
            } else {
                const float* bb = bias + 512;
#pragma unroll
                for (int j2 = 0; j2 < 8; j2++) {
                    int n0 = wn * 64 + j2 * 8 + 2 * t;
                    float p0 = 0.f, p1 = 0.f;
#pragma unroll
                    for (int mt = 0; mt < 2; mt++) {
                        int m0 = wm * 32 + mt * 16 + g;
                        bool v_lo = (tile * TILE_M + m0)     < NPAIR;
                        bool v_hi = (tile * TILE_M + m0 + 8) < NPAIR;
                        if (v_lo) { p0 += fmaxf(acc[mt][j2][0] + bb[n0],     0.f);
                                    p1 += fmaxf(acc[mt][j2][1] + bb[n0 + 1], 0.f); }
                        if (v_hi) { p0 += fmaxf(acc[mt][j2][2] + bb[n0],     0.f);
                                    p1 += fmaxf(acc[mt][j2][3] + bb[n0 + 1], 0.f); }
                    }
                    atomicAdd(&ssum[n0],     p0);
                    atomicAdd(&ssum[n0 + 1], p1);
                }
            }
        }
        __syncthreads();
    }

    if (tid < 256) atomicAdd(&d_xg[(size_t)b * HID + tid], ssum[tid]);
}

// ---------------------------------------------------------------------------
// f-MLP + log_softmax: 512 threads, batch-split halves, explicit layer unroll
// ---------------------------------------------------------------------------
__global__ void __launch_bounds__(512)
fnet_kernel(const float* __restrict__ fw1, const float* __restrict__ fb1,
            const float* __restrict__ fw2, const float* __restrict__ fb2,
            const float* __restrict__ fw3, const float* __restrict__ fb3,
            const float* __restrict__ fw4, const float* __restrict__ fb4,
            float* __restrict__ out, int B)
{
    const int tid = threadIdx.x;
    const int n = tid & 255;
    const int h = tid >> 8;                 // batch-half 0/1
    const int bb0 = blockIdx.x * 8;
    __shared__ float xa[8][HID];
    __shared__ float xb[8][HID];
    __shared__ float logit[8][16];

#pragma unroll
    for (int m = 0; m < 4; m++) {
        int mm = h * 4 + m;
        float v = 0.0f;
        if (bb0 + mm < B) v = d_xg[(size_t)(bb0 + mm) * HID + n];
        xa[mm][n] = v;
    }
    __syncthreads();

    // layer 1: xa -> xb
    {
        float acc[4] = {0.f, 0.f, 0.f, 0.f};
#pragma unroll 8
        for (int k = 0; k < HID; k++) {
            float wv = __ldg(&fw1[k * HID + n]);
#pragma unroll
            for (int m = 0; m < 4; m++) acc[m] += xa[h * 4 + m][k] * wv;
        }
        float bv = fb1[n];
#pragma unroll
        for (int m = 0; m < 4; m++) xb[h * 4 + m][n] = fmaxf(acc[m] + bv, 0.f);
    }
    __syncthreads();
    // layer 2: xb -> xa
    {
        float acc[4] = {0.f, 0.f, 0.f, 0.f};
#pragma unroll 8
        for (int k = 0; k < HID; k++) {
            float wv = __ldg(&fw2[k * HID + n]);
#pragma unroll
            for (int m = 0; m < 4; m++) acc[m] += xb[h * 4 + m][k] * wv;
        }
        float bv = fb2[n];
#pragma unroll
        for (int m = 0; m < 4; m++) xa[h * 4 + m][n] = fmaxf(acc[m] + bv, 0.f);
    }
    __syncthreads();
    // layer 3: xa -> xb
    {
        float acc[4] = {0.f, 0.f, 0.f, 0.f};
#pragma unroll 8
        for (int k = 0; k < HID; k++) {
            float wv = __ldg(&fw3[k * HID + n]);
#pragma unroll
            for (int m = 0; m < 4; m++) acc[m] += xa[h * 4 + m][k] * wv;
        }
        float bv = fb3[n];
#pragma unroll
        for (int m = 0; m < 4; m++) xb[h * 4 + m][n] = fmaxf(acc[m] + bv, 0.f);
    }
    __syncthreads();

    if (tid < 8 * N_CLS) {
        int m = tid / N_CLS, c = tid % N_CLS;
        float acc = fb4[c];
#pragma unroll 8
        for (int k = 0; k < HID; k++) acc += xb[m][k] * __ldg(&fw4[k * N_CLS + c]);
        logit[m][c] = acc;
    }
    __syncthreads();

    if (tid < 8 && (bb0 + tid) < B) {
        float mx = -INFINITY;
#pragma unroll
        for (int c = 0; c < N_CLS; c++) mx = fmaxf(mx, logit[tid][c]);
        float s = 0.0f;
#pragma unroll
        for (int c = 0; c < N_CLS; c++) s += expf(logit[tid][c] - mx);
        float lse = mx + logf(s);
#pragma unroll
        for (int c = 0; c < N_CLS; c++) out[(bb0 + tid) * N_CLS + c] = logit[tid][c] - lse;
    }
}

// ---------------------------------------------------------------------------
extern "C" void kernel_launch(void* const* d_in, const int* in_sizes, int n_in,
                              void* d_out, int out_size)
{
    const float* img  = (const float*)d_in[0];
    const float* qst  = (const float*)d_in[1];
    const float* g_w1 = (const float*)d_in[2];
    const float* g_b1 = (const float*)d_in[3];
    const float* g_w2 = (const float*)d_in[4];
    const float* g_b2 = (const float*)d_in[5];
    const float* g_w3 = (const float*)d_in[6];
    const float* g_b3 = (const float*)d_in[7];
    const float* g_w4 = (const float*)d_in[8];
    const float* g_b4 = (const float*)d_in[9];
    const float* f_w1 = (const float*)d_in[10];
    const float* f_b1 = (const float*)d_in[11];
    const float* f_w2 = (const float*)d_in[12];
    const float* f_b2 = (const float*)d_in[13];
    const float* f_w3 = (const float*)d_in[14];
    const float* f_b3 = (const float*)d_in[15];
    const float* f_w4 = (const float*)d_in[16];
    const float* f_b4 = (const float*)d_in[17];
    float* out = (float*)d_out;

    int B = in_sizes[0] / (N_OBJ * OBJ_F);
    if (B > MAXB) B = MAXB;

    const int smem_bytes = SMEM_FLOATS * 4;   // 201216
    cudaFuncSetAttribute(rn_mma_kernel, cudaFuncAttributeMaxDynamicSharedMemorySize,
                         smem_bytes);

    prearrange_w<<<3072, 32>>>(g_w2, g_w3, g_w4);
    prep_kernel<<<B, 256>>>(img, qst, g_w1, g_b1);
    rn_mma_kernel<<<dim3(NT, B), NTHREADS, smem_bytes>>>(g_b2, g_b3, g_b4);
    fnet_kernel<<<(B + 7) / 8, 512>>>(f_w1, f_b1, f_w2, f_b2, f_w3, f_b3, f_w4, f_b4, out, B);
}